// round 14
// baseline (speedup 1.0000x reference)
#include <cuda_runtime.h>

#define BB 8
#define CC 512
#define TT 8192
#define OPT 16              // outputs per thread
#define NT 128              // threads per block
#define CHUNK (NT * OPT)    // 2048 outputs per block
#define NCHUNK (TT / CHUNK) // 4 blocks per (b,c) row

__global__ __launch_bounds__(NT) void aa_fused_kernel(
    const float* __restrict__ x,
    const float* __restrict__ alpha,
    const float* __restrict__ beta,
    const float* __restrict__ fu,
    const float* __restrict__ fd,
    float* __restrict__ out)
{
    __shared__ float s_g0[6], s_F[6];
    __shared__ float s_a, s_ib;

    const int tid = threadIdx.x;
    const int bid = blockIdx.x;
    const int row = bid >> 2;       // NCHUNK == 4
    const int chunk = bid & 3;
    const int c = row & (CC - 1);

    // g0[r] = 2*fu[10-2r] (odd-n phase); even-n phase taps are g0 reversed
    // (kaiser filter symmetric, bit-exact). Down filter: fd[2d]=F[d], fd[2d+1]=F[5-d].
    if (tid < 6) {
        s_g0[tid] = 2.0f * fu[10 - 2 * tid];
    } else if (tid < 12) {
        const int d = tid - 6;
        const int map[6] = {0, 2, 4, 5, 3, 1};
        s_F[d] = fd[map[d]];
    } else if (tid == 12) {
        s_a = expf(alpha[c]);
    } else if (tid == 13) {
        s_ib = 1.0f / (expf(beta[c]) + 1e-9f);
    }
    __syncthreads();

    float g0r[6], F[6];
    #pragma unroll
    for (int r = 0; r < 6; r++) { g0r[r] = s_g0[r]; F[r] = s_F[r]; }
    const float a  = s_a;
    const float ib = s_ib;

    const float* xrow = x + (size_t)row * TT;
    float* orow = out + (size_t)row * TT;
    const int tb = chunk * CHUNK + tid * OPT;
    const int lane = tid & 31;

    const bool elo = (tb == 0);
    const bool ehi = (tb == TT - OPT);   // 8176

    // Logical window xq[j] = x[tb-8+j]; compute uses j = 3..28.
    float xq[32];

    // Own 16 floats: xq[8..23] = x[tb .. tb+15], aligned (tb % 16 == 0).
    {
        const float4* xv = (const float4*)(xrow + tb);
        #pragma unroll
        for (int v = 0; v < 4; v++) {
            float4 q = xv[v];
            xq[8 + 4 * v + 0] = q.x; xq[8 + 4 * v + 1] = q.y;
            xq[8 + 4 * v + 2] = q.z; xq[8 + 4 * v + 3] = q.w;
        }
    }

    // Left halo xq[3..7] = x[tb-5..tb-1] = left lane's xq[19..23].
    #pragma unroll
    for (int j = 0; j < 5; j++)
        xq[3 + j] = __shfl_up_sync(0xffffffffu, xq[19 + j], 1);
    // Right halo xq[24..28] = x[tb+16..tb+20] = right lane's xq[8..12].
    #pragma unroll
    for (int j = 0; j < 5; j++)
        xq[24 + j] = __shfl_down_sync(0xffffffffu, xq[8 + j], 1);

    // Lane 0: no left lane. Load x[tb-8..tb-1] (aligned) or replicate x[0] at row start.
    if (lane == 0) {
        if (elo) {
            #pragma unroll
            for (int j = 3; j < 8; j++) xq[j] = xq[8];
        } else {
            float4 qa = *(const float4*)(xrow + tb - 8);
            float4 qb = *(const float4*)(xrow + tb - 4);
            xq[3] = qa.w;
            xq[4] = qb.x; xq[5] = qb.y; xq[6] = qb.z; xq[7] = qb.w;
        }
    }
    // Lane 31: no right lane. Load x[tb+16..tb+20] or replicate x[8191] at row end.
    if (lane == 31) {
        if (ehi) {
            #pragma unroll
            for (int j = 24; j < 29; j++) xq[j] = xq[23];
        } else {
            float4 qa = *(const float4*)(xrow + tb + 16);
            float4 qb = *(const float4*)(xrow + tb + 20);
            xq[24] = qa.x; xq[25] = qa.y; xq[26] = qa.z; xq[27] = qa.w;
            xq[28] = qb.x;
        }
    }

    // zlo = z at upsampled n = 0 (row-left clamp target); xq[8..10] = x[tb..tb+2]
    float zlo;
    {
        const float x0 = xq[8], x1 = xq[9], x2 = xq[10];
        float accl = x0 * (g0r[5] + g0r[4] + g0r[3] + g0r[2])
                   + g0r[1] * x1 + g0r[0] * x2;
        const float sl = __sinf(accl * a);
        zlo = fmaf(sl * sl, ib, accl);
    }

    float o[OPT];
    float zh = 0.0f;

    // Stream pairs u = 0..20: z0 = z[s=2u] (n odd, taps g0),
    // z1 = z[s=2u+1] (n even, taps g0 reversed); window xq[3+u .. 8+u].
    // n = 2*tb - 5 + s. Scatter: o[u-d] += F[d]*z0 + F[5-d]*z1, d = 0..5.
    #pragma unroll
    for (int u = 0; u < 21; u++) {
        float acc0 = g0r[0] * xq[3 + u];
        float acc1 = g0r[5] * xq[3 + u];
        #pragma unroll
        for (int r = 1; r < 6; r++) {
            const float xv = xq[3 + u + r];
            acc0 = fmaf(g0r[r],     xv, acc0);
            acc1 = fmaf(g0r[5 - r], xv, acc1);
        }
        const float s0 = __sinf(acc0 * a);
        const float s1 = __sinf(acc1 * a);
        float z0 = fmaf(s0 * s0, ib, acc0);
        float z1 = fmaf(s1 * s1, ib, acc1);

        // row-left clamp: s < 5 (n < 0) -> z(n=0)
        if (u == 0 || u == 1) { z0 = elo ? zlo : z0; z1 = elo ? zlo : z1; }
        if (u == 2)           { z0 = elo ? zlo : z0; }
        // row-right clamp (tb = 8176): s > 36 (n > 2T-1) -> z(s=36) = z(n=2T-1)
        if (u == 18) { zh = z0; z1 = ehi ? zh : z1; }
        if (u >= 19) { z0 = ehi ? zh : z0; z1 = ehi ? zh : z1; }

        #pragma unroll
        for (int d = 0; d < 6; d++) {
            const int i = u - d;
            if (i >= 0 && i < OPT) {
                if (d == 0) o[i] = fmaf(F[0], z0, F[5] * z1);
                else        o[i] = fmaf(F[d], z0, fmaf(F[5 - d], z1, o[i]));
            }
        }

        if (u == 8)  *(float4*)(orow + tb)      = make_float4(o[0],  o[1],  o[2],  o[3]);
        if (u == 12) *(float4*)(orow + tb + 4)  = make_float4(o[4],  o[5],  o[6],  o[7]);
        if (u == 16) *(float4*)(orow + tb + 8)  = make_float4(o[8],  o[9],  o[10], o[11]);
        if (u == 20) *(float4*)(orow + tb + 12) = make_float4(o[12], o[13], o[14], o[15]);
    }
}

extern "C" void kernel_launch(void* const* d_in, const int* in_sizes, int n_in,
                              void* d_out, int out_size)
{
    const float* x     = (const float*)d_in[0];
    const float* alpha = (const float*)d_in[1];
    const float* beta  = (const float*)d_in[2];
    const float* fu    = (const float*)d_in[3];
    const float* fd    = (const float*)d_in[4];
    float* out = (float*)d_out;

    const int grid = BB * CC * NCHUNK; // 16384
    aa_fused_kernel<<<grid, NT>>>(x, alpha, beta, fu, fd, out);
}

// round 15
// speedup vs baseline: 1.5685x; 1.5685x over previous
#include <cuda_runtime.h>

#define BB 8
#define CC 512
#define TT 8192
#define OPT 16              // outputs per thread
#define NT 128              // threads per block
#define CHUNK (NT * OPT)    // 2048 outputs per block
#define NCHUNK (TT / CHUNK) // 4 blocks per (b,c) row

union V8 { ulonglong4 u; float f[8]; };

__global__ __launch_bounds__(NT) void aa_fused_kernel(
    const float* __restrict__ x,
    const float* __restrict__ alpha,
    const float* __restrict__ beta,
    const float* __restrict__ fu,
    const float* __restrict__ fd,
    float* __restrict__ out)
{
    __shared__ float s_g0[6], s_F[6];
    __shared__ float s_a, s_ib;

    const int tid = threadIdx.x;
    const int bid = blockIdx.x;
    const int row = bid >> 2;       // NCHUNK == 4
    const int chunk = bid & 3;
    const int c = row & (CC - 1);

    // g0[r] = 2*fu[10-2r] (odd-n phase); even-n phase taps are g0 reversed
    // (kaiser filter symmetric, bit-exact). Down filter: fd[2d]=F[d], fd[2d+1]=F[5-d].
    if (tid < 6) {
        s_g0[tid] = 2.0f * fu[10 - 2 * tid];
    } else if (tid < 12) {
        const int d = tid - 6;
        const int map[6] = {0, 2, 4, 5, 3, 1};
        s_F[d] = fd[map[d]];
    } else if (tid == 12) {
        s_a = expf(alpha[c]);
    } else if (tid == 13) {
        s_ib = 1.0f / (expf(beta[c]) + 1e-9f);
    }
    __syncthreads();

    float g0r[6], F[6];
    #pragma unroll
    for (int r = 0; r < 6; r++) { g0r[r] = s_g0[r]; F[r] = s_F[r]; }
    const float a  = s_a;
    const float ib = s_ib;

    const float* xrow = x + (size_t)row * TT;
    float* orow = out + (size_t)row * TT;
    const int tb = chunk * CHUNK + tid * OPT;

    const bool elo = (tb == 0);
    const bool ehi = (tb == TT - OPT);   // 8176

    // x window: xq[j] = x[tb-8+j], j=0..31 (compute uses 3..28)
    float xq[32];
    if (!elo && !ehi) {
        // 256-bit loads: (tb-8)*4 bytes is a 32B multiple (tb % 16 == 0)
        const ulonglong4* xv = (const ulonglong4*)(xrow + tb - 8);
        #pragma unroll
        for (int v = 0; v < 4; v++) {
            V8 w; w.u = xv[v];
            #pragma unroll
            for (int j = 0; j < 8; j++) xq[8 * v + j] = w.f[j];
        }
    } else {
        #pragma unroll
        for (int v = 0; v < 8; v++) {
            int base = tb - 8 + 4 * v;
            base = min(max(base, 0), TT - 4);           // legal aligned load
            float4 q = *(const float4*)(xrow + base);
            xq[4 * v + 0] = q.x; xq[4 * v + 1] = q.y;
            xq[4 * v + 2] = q.z; xq[4 * v + 3] = q.w;
        }
        if (elo) {
            const float x0 = xq[8];                     // x[0]
            #pragma unroll
            for (int j = 0; j < 8; j++) xq[j] = x0;     // replicate pad x[-8..-1]
        }
        if (ehi) {
            const float xN = xq[23];                    // x[8191]
            #pragma unroll
            for (int j = 24; j < 32; j++) xq[j] = xN;   // replicate pad x[8192..]
        }
    }

    // zlo = z at upsampled n = 0 (row-left clamp target); xq[8..10] = x[tb..tb+2]
    float zlo;
    {
        const float x0 = xq[8], x1 = xq[9], x2 = xq[10];
        float accl = x0 * (g0r[5] + g0r[4] + g0r[3] + g0r[2])
                   + g0r[1] * x1 + g0r[0] * x2;
        const float sl = __sinf(accl * a);
        zlo = fmaf(sl * sl, ib, accl);
    }

    float o[OPT];
    float zh = 0.0f;

    // Stream z pairs: u = 0..20; z0 = z[s=2u] (n odd, taps g0),
    // z1 = z[s=2u+1] (n even, taps g0 reversed); shared window xq[3+u .. 8+u].
    // n = 2*tb - 5 + s. Scatter: o[u-d] += F[d]*z0 + F[5-d]*z1, d = 0..5.
    #pragma unroll
    for (int u = 0; u < 21; u++) {
        float acc0 = g0r[0] * xq[3 + u];
        float acc1 = g0r[5] * xq[3 + u];
        #pragma unroll
        for (int r = 1; r < 6; r++) {
            const float xv = xq[3 + u + r];
            acc0 = fmaf(g0r[r],     xv, acc0);
            acc1 = fmaf(g0r[5 - r], xv, acc1);
        }
        const float s0 = __sinf(acc0 * a);
        const float s1 = __sinf(acc1 * a);
        float z0 = fmaf(s0 * s0, ib, acc0);
        float z1 = fmaf(s1 * s1, ib, acc1);

        // row-left clamp: s < 5 (n < 0) -> z(n=0)
        if (u == 0 || u == 1) { z0 = elo ? zlo : z0; z1 = elo ? zlo : z1; }
        if (u == 2)           { z0 = elo ? zlo : z0; }
        // row-right clamp (tb = 8176): s > 36 (n > 2T-1) -> z(s=36) = z(n=2T-1)
        if (u == 18) { zh = z0; z1 = ehi ? zh : z1; }
        if (u >= 19) { z0 = ehi ? zh : z0; z1 = ehi ? zh : z1; }

        #pragma unroll
        for (int d = 0; d < 6; d++) {
            const int i = u - d;
            if (i >= 0 && i < OPT) {
                if (d == 0) o[i] = fmaf(F[0], z0, F[5] * z1);
                else        o[i] = fmaf(F[d], z0, fmaf(F[5 - d], z1, o[i]));
            }
        }

        // 256-bit stores: orow+tb and orow+tb+8 are 32B-aligned (tb % 16 == 0)
        if (u == 12) {
            V8 w;
            #pragma unroll
            for (int j = 0; j < 8; j++) w.f[j] = o[j];
            *(ulonglong4*)(orow + tb) = w.u;
        }
        if (u == 20) {
            V8 w;
            #pragma unroll
            for (int j = 0; j < 8; j++) w.f[j] = o[8 + j];
            *(ulonglong4*)(orow + tb + 8) = w.u;
        }
    }
}

extern "C" void kernel_launch(void* const* d_in, const int* in_sizes, int n_in,
                              void* d_out, int out_size)
{
    const float* x     = (const float*)d_in[0];
    const float* alpha = (const float*)d_in[1];
    const float* beta  = (const float*)d_in[2];
    const float* fu    = (const float*)d_in[3];
    const float* fd    = (const float*)d_in[4];
    float* out = (float*)d_out;

    const int grid = BB * CC * NCHUNK; // 16384
    aa_fused_kernel<<<grid, NT>>>(x, alpha, beta, fu, fd, out);
}